// round 5
// baseline (speedup 1.0000x reference)
#include <cuda_runtime.h>
#include <cuda_fp16.h>

// B=16, C=64, H=W=256, STRIDE=2, IN_KS=OUT_KS=3
#define HH 256
#define WW 256
#define HP 128
#define WP 128
#define TH 32              // output rows per block
#define NT 8               // tiles per plane
#define CAN_H 34           // image rows R0-1 .. R0+32
#define CAN_WH 264         // halves per canvas row (258 used; 528B, 16B-aligned)
#define PR_H 19            // prov rows I0-1 .. I0+17
#define PR_W 136           // ushort; cell j at index j+4, halos at 3 and 132

__device__ __forceinline__ unsigned hmax2u(unsigned a, unsigned b) {
    __half2 r = __hmax2(*(__half2*)&a, *(__half2*)&b);
    return *(unsigned*)&r;
}

__global__ __launch_bounds__(256, 8)
void morph_unpool_dilate_kernel(const float* __restrict__ f,
                                const int*   __restrict__ prov,
                                float*       __restrict__ out)
{
    __shared__ __align__(16) __half    canvas[CAN_H][CAN_WH];
    __shared__ unsigned short          sprov[PR_H][PR_W];

    const int bid  = blockIdx.x;
    const int bc   = bid >> 3;
    const int tile = bid & 7;
    const int R0   = tile * TH;
    const int I0   = tile * (TH / 2);
    const int tid  = threadIdx.x;
    const int lane = tid & 31;

    const float4* fb4 = (const float4*)(f + (size_t)bc * (HP * WP));
    const int4*   pb4 = (const int4*)  (prov + (size_t)bc * (HP * WP));

    // ---- Phase 1a: unconditional uint4 zero-fill of canvas ----
    {
        uint4  z  = make_uint4(0u, 0u, 0u, 0u);
        uint4* c4 = (uint4*)&canvas[0][0];
        #pragma unroll
        for (int i = tid; i < CAN_H * (CAN_WH / 8); i += 256) c4[i] = z;
    }

    // ---- Phase 1b: stage provenance as u16 (int4 loads, ushort4 stores) ----
    for (int idx = tid; idx < PR_H * 32; idx += 256) {
        int li = idx >> 5;                  // cell row i = I0-1+li
        int g  = idx & 31;
        int i  = I0 - 1 + li;
        ushort4 s = make_ushort4(0, 0, 0, 0);   // top/bottom sentinel
        if ((unsigned)i < HP) {
            int4 p = pb4[i * 32 + g];
            s = make_ushort4((unsigned short)p.x, (unsigned short)p.y,
                             (unsigned short)p.z, (unsigned short)p.w);
        }
        *(ushort4*)&sprov[li][(g << 2) + 4] = s;
    }
    if (tid < PR_H * 2) {                   // column halos
        int li = tid >> 1;
        if (tid & 1) sprov[li][132] = 0;        // j=128 (comparers have c>=254)
        else         sprov[li][3]   = 0xFFFF;   // j=-1  (comparers have c<=2)
    }
    __syncthreads();

    // ---- Phase 2a: -inf borders (never scatter targets; after barrier) ----
    if (tid < CAN_H * 2) {
        int r = tid >> 1;
        ((unsigned short*)&canvas[r][0])[(tid & 1) ? 257 : 0] = 0xFC00;
    }
    if (tile == 0 && tid < CAN_WH / 8)
        ((uint4*)&canvas[0][0])[tid] =
            make_uint4(0xFC00FC00u, 0xFC00FC00u, 0xFC00FC00u, 0xFC00FC00u);
    if (tile == NT - 1 && tid < CAN_WH / 8)
        ((uint4*)&canvas[CAN_H - 1][0])[tid] =
            make_uint4(0xFC00FC00u, 0xFC00FC00u, 0xFC00FC00u, 0xFC00FC00u);

    // ---- Phase 2b: race-free last-write-wins scatter (R3 vectorized form) ----
    // Cell (i,j) writes iff none of (i,j+1),(i+1,j-1),(i+1,j),(i+1,j+1)
    // (all higher linear index) targets the same pixel.
    for (int idx = tid; idx < 18 * 32; idx += 256) {
        int li = idx >> 5;
        int g  = idx & 31;
        int i  = I0 - 1 + li;
        if ((unsigned)i < HP) {
            int j = g << 2;
            ushort4 o  = *(const ushort4*)&sprov[li][j + 4];
            ushort4 bw = *(const ushort4*)&sprov[li + 1][j + 4];
            int rr = sprov[li][j + 8];
            int bl = sprov[li + 1][j + 3];
            int br = sprov[li + 1][j + 8];
            float4 fv = fb4[i * 32 + g];
            int t0 = o.x,  t1 = o.y,  t2 = o.z,  t3 = o.w;
            int b0 = bw.x, b1 = bw.y, b2 = bw.z, b3 = bw.w;

            #define SCATTER(t, n1, n2, n3, n4, val)                          \
            {                                                                \
                bool sup = ((n1) == (t)) | ((n2) == (t)) |                   \
                           ((n3) == (t)) | ((n4) == (t));                    \
                int lr = ((t) >> 8) - R0 + 1;                                \
                if (!sup && (unsigned)lr < CAN_H)                            \
                    canvas[lr][((t) & 255) + 1] = __float2half_rn(val);      \
            }
            SCATTER(t0, t1, bl, b0, b1, fv.x);
            SCATTER(t1, t2, b0, b1, b2, fv.y);
            SCATTER(t2, t3, b1, b2, b3, fv.z);
            SCATTER(t3, rr, b2, b3, br, fv.w);
            #undef SCATTER
        }
    }
    __syncthreads();

    // ---- Phase 3: separable 3x3 max in half2, 8-col x 4-row strips ----
    // Warp-uniform strip: lane = col group (8 output cols), tid>>5 = row strip.
    const int  s    = tid >> 5;            // 0..7
    const int  base = s << 2;              // local output row base (4 rows)
    float* ob = out + (size_t)bc * (HH * WW) + (size_t)(R0 + base) * WW + (lane << 3);

    struct H4 { unsigned p0, p1, p2, p3; };
    auto hrow = [&](int cr) -> H4 {
        const unsigned* row = (const unsigned*)&canvas[cr][0];
        uint4 A = ((const uint4*)row)[lane];              // halves 8l..8l+7
        unsigned vh = __shfl_down_sync(0xffffffffu, A.x, 1); // halves 8l+8,8l+9
        if (lane == 31) vh = row[128];                    // halves 256,257
        unsigned s0 = __byte_perm(A.x, A.y, 0x5432);      // (a1,a2)
        unsigned s1 = __byte_perm(A.y, A.z, 0x5432);
        unsigned s2 = __byte_perm(A.z, A.w, 0x5432);
        unsigned s3 = __byte_perm(A.w, vh,  0x5432);
        H4 h;
        h.p0 = hmax2u(hmax2u(A.x, s0), A.y);
        h.p1 = hmax2u(hmax2u(A.y, s1), A.z);
        h.p2 = hmax2u(hmax2u(A.z, s2), A.w);
        h.p3 = hmax2u(hmax2u(A.w, s3), vh);
        return h;
    };

    H4 h0 = hrow(base);
    H4 h1 = hrow(base + 1);
    #pragma unroll
    for (int k = 0; k < 4; k++) {
        H4 h2 = hrow(base + k + 2);
        unsigned o0 = hmax2u(hmax2u(h0.p0, h1.p0), h2.p0);
        unsigned o1 = hmax2u(hmax2u(h0.p1, h1.p1), h2.p1);
        unsigned o2 = hmax2u(hmax2u(h0.p2, h1.p2), h2.p2);
        unsigned o3 = hmax2u(hmax2u(h0.p3, h1.p3), h2.p3);
        float2 f0 = __half22float2(*(__half2*)&o0);
        float2 f1 = __half22float2(*(__half2*)&o1);
        float2 f2 = __half22float2(*(__half2*)&o2);
        float2 f3 = __half22float2(*(__half2*)&o3);
        *(float4*)&ob[k * WW]     = make_float4(f0.x, f0.y, f1.x, f1.y);
        *(float4*)&ob[k * WW + 4] = make_float4(f2.x, f2.y, f3.x, f3.y);
        h0 = h1; h1 = h2;
    }
}

extern "C" void kernel_launch(void* const* d_in, const int* in_sizes, int n_in,
                              void* d_out, int out_size)
{
    const float* f    = (const float*)d_in[0];
    const int*   prov = (const int*)  d_in[1];
    float* out = (float*)d_out;
    morph_unpool_dilate_kernel<<<1024 * NT, 256>>>(f, prov, out);
}

// round 6
// speedup vs baseline: 1.6015x; 1.6015x over previous
#include <cuda_runtime.h>

// B=16, C=64, H=W=256, STRIDE=2, IN_KS=OUT_KS=3
#define HH 256
#define WW 256
#define HP 128
#define WP 128
#define TH 16              // output rows per block
#define NT 16              // tiles per plane
#define CAN_H 18           // image rows R0-1 .. R0+16
#define CAN_W 260          // 258 used, padded for float4
#define PR_H 11            // prov rows I0-1 .. I0+9 (row 10 = neighbor/sentinel)
#define PR_W 136           // ushort; cell j at index j+4, halos at 3 and 132

__global__ __launch_bounds__(256, 7)
void morph_unpool_dilate_kernel(const float* __restrict__ f,
                                const int*   __restrict__ prov,
                                float*       __restrict__ out)
{
    __shared__ float          canvas[CAN_H][CAN_W];
    __shared__ unsigned short sprov[PR_H][PR_W];

    const int   bid  = blockIdx.x;
    const int   bc   = bid >> 4;          // plane (b*c)
    const int   tile = bid & 15;
    const int   R0   = tile * TH;
    const int   I0   = tile * (TH / 2);
    const int   tid  = threadIdx.x;
    const float NEG  = __int_as_float(0xff800000);

    const float4* fb4 = (const float4*)(f + (size_t)bc * (HP * WP));
    const int4*   pb4 = (const int4*)  (prov + (size_t)bc * (HP * WP));

    // ---- Phase 1a: unconditional float4 zero-fill of canvas ----
    {
        float4  z  = make_float4(0.f, 0.f, 0.f, 0.f);
        float4* c4 = (float4*)&canvas[0][0];
        #pragma unroll
        for (int i = tid; i < CAN_H * 65; i += 256) c4[i] = z;
    }

    // ---- Phase 1b: stage provenance as u16 (int4 loads, ushort4 stores) ----
    for (int idx = tid; idx < PR_H * 32; idx += 256) {
        int li = idx >> 5;                  // cell row i = I0-1+li
        int g  = idx & 31;
        int i  = I0 - 1 + li;
        ushort4 s = make_ushort4(0, 0, 0, 0);   // out-of-range sentinel
        if ((unsigned)i < HP) {
            int4 p = pb4[i * 32 + g];
            s = make_ushort4((unsigned short)p.x, (unsigned short)p.y,
                             (unsigned short)p.z, (unsigned short)p.w);
        }
        *(ushort4*)&sprov[li][(g << 2) + 4] = s;
    }
    if (tid < PR_H * 2) {                   // column halos
        int li = tid >> 1;
        if (tid & 1) sprov[li][132] = 0;        // j=128 (comparers have c>=254)
        else         sprov[li][3]   = 0xFFFF;   // j=-1  (comparers have c<=2)
    }
    __syncthreads();

    // ---- Phase 2a: -inf borders (addresses never targeted by the scatter) ----
    if (tid < CAN_H * 2) {
        int r = tid >> 1;
        canvas[r][(tid & 1) ? (WW + 1) : 0] = NEG;
    }
    if (tile == 0 && tid < 65)
        ((float4*)&canvas[0][0])[tid] = make_float4(NEG, NEG, NEG, NEG);
    if (tile == NT - 1 && tid < 65)
        ((float4*)&canvas[CAN_H - 1][0])[tid] = make_float4(NEG, NEG, NEG, NEG);

    // ---- Phase 2b: race-free last-write-wins scatter (R3 vectorized form) ----
    // Cell (i,j) writes iff none of (i,j+1),(i+1,j-1),(i+1,j),(i+1,j+1)
    // (all higher linear index) targets the same pixel.
    for (int idx = tid; idx < 10 * 32; idx += 256) {
        int li = idx >> 5;
        int g  = idx & 31;
        int i  = I0 - 1 + li;
        if ((unsigned)i < HP) {
            int j = g << 2;
            ushort4 o  = *(const ushort4*)&sprov[li][j + 4];
            ushort4 bw = *(const ushort4*)&sprov[li + 1][j + 4];
            int rr = sprov[li][j + 8];
            int bl = sprov[li + 1][j + 3];
            int br = sprov[li + 1][j + 8];
            float4 fv = fb4[i * 32 + g];
            int t0 = o.x,  t1 = o.y,  t2 = o.z,  t3 = o.w;
            int b0 = bw.x, b1 = bw.y, b2 = bw.z, b3 = bw.w;

            #define SCATTER(t, n1, n2, n3, n4, val)                          \
            {                                                                \
                bool sup = ((n1) == (t)) | ((n2) == (t)) |                   \
                           ((n3) == (t)) | ((n4) == (t));                    \
                int lr = ((t) >> 8) - R0 + 1;                                \
                if (!sup && (unsigned)lr < CAN_H)                            \
                    canvas[lr][((t) & 255) + 1] = (val);                     \
            }
            SCATTER(t0, t1, bl, b0, b1, fv.x);
            SCATTER(t1, t2, b0, b1, b2, fv.y);
            SCATTER(t2, t3, b1, b2, b3, fv.z);
            SCATTER(t3, rr, b2, b3, br, fv.w);
            #undef SCATTER
        }
    }
    __syncthreads();

    // ---- Phase 3: separable 3x3 max, 4-row strips, rolling vertical max ----
    // Thread: col group cb..cb+3, 4 consecutive output rows; 6 canvas row loads.
    const int cb   = (tid & 63) << 2;
    const int base = (tid >> 6) << 2;
    float* ob = out + (size_t)bc * (HH * WW) + (size_t)(R0 + base) * WW + cb;

    auto hrow = [&](int cr) -> float4 {
        float4 a = *(const float4*)&canvas[cr][cb];
        float2 b = *(const float2*)&canvas[cr][cb + 4];
        float  m = fmaxf(a.y, a.z);
        float  n = fmaxf(a.w, b.x);
        float4 h;
        h.x = fmaxf(m, a.x);
        h.y = fmaxf(m, a.w);
        h.z = fmaxf(a.z, n);
        h.w = fmaxf(n, b.y);
        return h;
    };

    float4 h0 = hrow(base);
    float4 h1 = hrow(base + 1);
    #pragma unroll
    for (int k = 0; k < 4; k++) {
        float4 h2 = hrow(base + k + 2);
        float4 o;
        o.x = fmaxf(fmaxf(h0.x, h1.x), h2.x);
        o.y = fmaxf(fmaxf(h0.y, h1.y), h2.y);
        o.z = fmaxf(fmaxf(h0.z, h1.z), h2.z);
        o.w = fmaxf(fmaxf(h0.w, h1.w), h2.w);
        *(float4*)&ob[k * WW] = o;
        h0 = h1; h1 = h2;
    }
}

extern "C" void kernel_launch(void* const* d_in, const int* in_sizes, int n_in,
                              void* d_out, int out_size)
{
    const float* f    = (const float*)d_in[0];
    const int*   prov = (const int*)  d_in[1];
    float* out = (float*)d_out;
    morph_unpool_dilate_kernel<<<1024 * NT, 256>>>(f, prov, out);
}